// round 16
// baseline (speedup 1.0000x reference)
#include <cuda_runtime.h>
#include <cuda_bf16.h>
#include <cstdint>

#define D 128
#define MAXN 100000
#define MAXE 1600000
#define STR 136   // bf16 row stride in smem (272B -> conflict-free ldmatrix)

// ---- static scratch (no allocations allowed) ----
__device__ float g_tmp[(size_t)MAXN * D];
__device__ float g_h1 [(size_t)MAXN * D];
__device__ float g_h  [(size_t)MAXN * D];
__device__ int   g_counts[MAXN];
__device__ int   g_rptr [MAXN + 1];
__device__ int   g_cursor[MAXN];
__device__ int   g_boff [256];
__device__ int   g_csrc [MAXE];
__device__ float g_cw   [MAXE];

// ---------------- CSR build ----------------
__global__ void hist_kernel(const int* __restrict__ dst, int E) {
    int e = blockIdx.x * blockDim.x + threadIdx.x;
    if (e < E) atomicAdd(&g_counts[dst[e]], 1);
}

__global__ void scan1_kernel(int n) {
    __shared__ int wsum[32];
    int tid = threadIdx.x, lane = tid & 31, wid = tid >> 5;
    int i = blockIdx.x * 1024 + tid;
    int v = (i < n) ? g_counts[i] : 0;
    int incl = v;
    #pragma unroll
    for (int d = 1; d < 32; d <<= 1) {
        int t = __shfl_up_sync(0xffffffffu, incl, d);
        if (lane >= d) incl += t;
    }
    if (lane == 31) wsum[wid] = incl;
    __syncthreads();
    if (wid == 0) {
        int s = wsum[lane];
        #pragma unroll
        for (int d = 1; d < 32; d <<= 1) {
            int t = __shfl_up_sync(0xffffffffu, s, d);
            if (lane >= d) s += t;
        }
        wsum[lane] = s;
    }
    __syncthreads();
    int add = wid ? wsum[wid - 1] : 0;
    int excl = add + incl - v;
    if (i < n) g_rptr[i] = excl;
    if (tid == 1023) g_boff[blockIdx.x] = excl + v;
}

__global__ void scan2_kernel(int nb) {
    __shared__ int wsum[8];
    int tid = threadIdx.x, lane = tid & 31, wid = tid >> 5;
    int v = (tid < nb) ? g_boff[tid] : 0;
    int incl = v;
    #pragma unroll
    for (int d = 1; d < 32; d <<= 1) {
        int t = __shfl_up_sync(0xffffffffu, incl, d);
        if (lane >= d) incl += t;
    }
    if (lane == 31) wsum[wid] = incl;
    __syncthreads();
    if (wid == 0 && lane < 8) {
        int s = wsum[lane];
        #pragma unroll
        for (int d = 1; d < 8; d <<= 1) {
            int t = __shfl_up_sync(0xffu, s, d);
            if (lane >= d) s += t;
        }
        wsum[lane] = s;
    }
    __syncthreads();
    int add = wid ? wsum[wid - 1] : 0;
    if (tid < nb) g_boff[tid] = add + incl - v;
}

__global__ void scan3_kernel(int n, int E) {
    int i = blockIdx.x * 1024 + threadIdx.x;
    if (i < n) {
        int v = g_rptr[i] + g_boff[blockIdx.x];
        g_rptr[i] = v;
        g_cursor[i] = v;
    }
    if (i == 0) g_rptr[n] = E;
}

__global__ void scatter_kernel(const int* __restrict__ src, const int* __restrict__ dst,
                               const float* __restrict__ w, int E) {
    int e = blockIdx.x * blockDim.x + threadIdx.x;
    if (e < E) {
        int d = dst[e];
        int p = atomicAdd(&g_cursor[d], 1);
        g_csrc[p] = src[e];
        g_cw[p]   = w[e];
    }
}

// ================= HMMA (mma.sync) helpers =================
__device__ __forceinline__ uint32_t smem_u32(const void* p) {
    uint32_t a;
    asm("{ .reg .u64 t; cvta.to.shared.u64 t, %1; cvt.u32.u64 %0, t; }" : "=r"(a) : "l"(p));
    return a;
}
__device__ __forceinline__ void ldsm_x4(uint32_t* r, uint32_t addr) {
    asm volatile("ldmatrix.sync.aligned.m8n8.x4.shared.b16 {%0,%1,%2,%3}, [%4];"
                 : "=r"(r[0]), "=r"(r[1]), "=r"(r[2]), "=r"(r[3]) : "r"(addr));
}
__device__ __forceinline__ void ldsm_x4_t(uint32_t* r, uint32_t addr) {
    asm volatile("ldmatrix.sync.aligned.m8n8.x4.trans.shared.b16 {%0,%1,%2,%3}, [%4];"
                 : "=r"(r[0]), "=r"(r[1]), "=r"(r[2]), "=r"(r[3]) : "r"(addr));
}
__device__ __forceinline__ void mma_bf16(float* c, const uint32_t* a, uint32_t b0, uint32_t b1) {
    asm volatile("mma.sync.aligned.m16n8k16.row.col.f32.bf16.bf16.f32 "
                 "{%0,%1,%2,%3}, {%4,%5,%6,%7}, {%8,%9}, {%0,%1,%2,%3};"
                 : "+f"(c[0]), "+f"(c[1]), "+f"(c[2]), "+f"(c[3])
                 : "r"(a[0]), "r"(a[1]), "r"(a[2]), "r"(a[3]), "r"(b0), "r"(b1));
}
__device__ __forceinline__ uint32_t pack_hi(float x, float y, uint32_t& lo_out) {
    __nv_bfloat16 hx = __float2bfloat16_rn(x);
    __nv_bfloat16 hy = __float2bfloat16_rn(y);
    __nv_bfloat16 lx = __float2bfloat16_rn(x - __bfloat162float(hx));
    __nv_bfloat16 ly = __float2bfloat16_rn(y - __bfloat162float(hy));
    lo_out = (uint32_t)__bfloat16_as_ushort(lx) | ((uint32_t)__bfloat16_as_ushort(ly) << 16);
    return (uint32_t)__bfloat16_as_ushort(hx) | ((uint32_t)__bfloat16_as_ushort(hy) << 16);
}

// ---------------- GEMM via mma.sync: Y[n,128] = X[n,128] @ W[128,128] ----------------
// bf16 two-term split (Xh·Wh + Xl·Wh + Xh·Wl), fp32 accum.
// 512 threads = 16 warps in 4x4 grid; warp tile 32 rows x 32 cols.
// Double-buffered ldmatrix fragments to hide LDS latency.
__global__ void __launch_bounds__(512, 1)
gemm128_kernel(const float* __restrict__ X, const float* __restrict__ W,
               float* __restrict__ Y, int nrows) {
    extern __shared__ char smc[];
    uint32_t sbase = smem_u32(smc);
    const uint32_t SZA = 128 * STR * 2;       // 34816 B per array
    uint32_t sAhi = sbase, sAlo = sbase + SZA, sWhi = sbase + 2 * SZA, sWlo = sbase + 3 * SZA;
    int tid = threadIdx.x, lane = tid & 31, w = tid >> 5;
    int wm = w >> 2, wn = w & 3;
    int row0 = blockIdx.x * 128;

    // --- prep W: hi/lo bf16 ---
    {
        int r = tid >> 2, q = (tid & 3) * 32;
        const float2* src = (const float2*)&W[r * 128 + q];
        uint32_t* dh = (uint32_t*)(smc + 2 * SZA) + (r * STR + q) / 2;
        uint32_t* dl = (uint32_t*)(smc + 3 * SZA) + (r * STR + q) / 2;
        #pragma unroll
        for (int i = 0; i < 16; i++) {
            float2 v = src[i];
            uint32_t lo;
            uint32_t hi = pack_hi(v.x, v.y, lo);
            dh[i] = hi; dl[i] = lo;
        }
    }
    // --- prep X tile ---
    {
        int r = tid >> 2, q = (tid & 3) * 32;
        int gr = row0 + r;
        uint32_t* dh = (uint32_t*)smc + (r * STR + q) / 2;
        uint32_t* dl = (uint32_t*)(smc + SZA) + (r * STR + q) / 2;
        if (gr < nrows) {
            const float2* src = (const float2*)&X[(size_t)gr * 128 + q];
            #pragma unroll
            for (int i = 0; i < 16; i++) {
                float2 v = src[i];
                uint32_t lo;
                uint32_t hi = pack_hi(v.x, v.y, lo);
                dh[i] = hi; dl[i] = lo;
            }
        } else {
            #pragma unroll
            for (int i = 0; i < 16; i++) { dh[i] = 0u; dl[i] = 0u; }
        }
    }
    __syncthreads();

    // acc[mt][nt][g][4]: mt,nt in {0,1}; g = n8 group
    float acc[2][2][2][4];
    #pragma unroll
    for (int mt = 0; mt < 2; mt++)
        #pragma unroll
        for (int nt = 0; nt < 2; nt++)
            #pragma unroll
            for (int g = 0; g < 2; g++)
                #pragma unroll
                for (int c = 0; c < 4; c++) acc[mt][nt][g][c] = 0.f;

    // lane base offsets (bytes)
    uint32_t aoff[2], boff[2];
    #pragma unroll
    for (int mt = 0; mt < 2; mt++)
        aoff[mt] = (uint32_t)(((wm * 32 + mt * 16 + (lane & 15)) * STR + (lane >> 4) * 8) * 2);
    #pragma unroll
    for (int nt = 0; nt < 2; nt++)
        boff[nt] = (uint32_t)(((lane & 15) * STR + wn * 32 + nt * 16 + (lane >> 4) * 8) * 2);

    // double-buffered fragments
    uint32_t Ah[2][2][4], Al[2][2][4], Bh[2][2][4], Bl[2][2][4];

    #define LOAD_FRAGS(buf, kc) do {                                          \
        _Pragma("unroll")                                                     \
        for (int mt = 0; mt < 2; mt++) {                                      \
            ldsm_x4(Ah[buf][mt], sAhi + aoff[mt] + (uint32_t)((kc) * 32));    \
            ldsm_x4(Al[buf][mt], sAlo + aoff[mt] + (uint32_t)((kc) * 32));    \
        }                                                                     \
        _Pragma("unroll")                                                     \
        for (int nt = 0; nt < 2; nt++) {                                      \
            ldsm_x4_t(Bh[buf][nt], sWhi + boff[nt] + (uint32_t)((kc) * 16 * STR * 2)); \
            ldsm_x4_t(Bl[buf][nt], sWlo + boff[nt] + (uint32_t)((kc) * 16 * STR * 2)); \
        }                                                                     \
    } while (0)

    #define COMPUTE(buf) do {                                                 \
        _Pragma("unroll")                                                     \
        for (int mt = 0; mt < 2; mt++)                                        \
            _Pragma("unroll")                                                 \
            for (int nt = 0; nt < 2; nt++) {                                  \
                float* c0 = acc[mt][nt][0];                                   \
                float* c1 = acc[mt][nt][1];                                   \
                mma_bf16(c0, Ah[buf][mt], Bh[buf][nt][0], Bh[buf][nt][1]);    \
                mma_bf16(c0, Al[buf][mt], Bh[buf][nt][0], Bh[buf][nt][1]);    \
                mma_bf16(c0, Ah[buf][mt], Bl[buf][nt][0], Bl[buf][nt][1]);    \
                mma_bf16(c1, Ah[buf][mt], Bh[buf][nt][2], Bh[buf][nt][3]);    \
                mma_bf16(c1, Al[buf][mt], Bh[buf][nt][2], Bh[buf][nt][3]);    \
                mma_bf16(c1, Ah[buf][mt], Bl[buf][nt][2], Bl[buf][nt][3]);    \
            }                                                                 \
    } while (0)

    LOAD_FRAGS(0, 0);
    #pragma unroll
    for (int kc = 0; kc < 8; kc++) {
        if (kc < 7) LOAD_FRAGS((kc + 1) & 1, kc + 1);
        COMPUTE(kc & 1);
    }
    #undef LOAD_FRAGS
    #undef COMPUTE

    // --- epilogue ---
    #pragma unroll
    for (int mt = 0; mt < 2; mt++) {
        int rbase = row0 + wm * 32 + mt * 16 + (lane >> 2);
        bool ok0 = rbase < nrows, ok1 = (rbase + 8) < nrows;
        #pragma unroll
        for (int nt = 0; nt < 2; nt++)
            #pragma unroll
            for (int g = 0; g < 2; g++) {
                int col = wn * 32 + nt * 16 + g * 8 + 2 * (lane & 3);
                float* c = acc[mt][nt][g];
                if (ok0) *(float2*)&Y[(size_t)rbase * 128 + col]       = make_float2(c[0], c[1]);
                if (ok1) *(float2*)&Y[(size_t)(rbase + 8) * 128 + col] = make_float2(c[2], c[3]);
            }
    }
}

// ---------------- SpMM (CSR gather) + bias + relu (+ residual add) ----------------
__global__ void spmm_kernel(const float* __restrict__ x, const float* __restrict__ bias,
                            float* __restrict__ out, const float* __restrict__ addsrc, int n) {
    int warp = (blockIdx.x * blockDim.x + threadIdx.x) >> 5;
    int lane = threadIdx.x & 31;
    if (warp >= n) return;
    int s = g_rptr[warp], e = g_rptr[warp + 1];
    const float4* x4 = (const float4*)x;
    float4 acc = make_float4(0.f, 0.f, 0.f, 0.f);
    int i = s;
    for (; i + 3 < e; i += 4) {
        int s0 = g_csrc[i], s1 = g_csrc[i + 1], s2 = g_csrc[i + 2], s3 = g_csrc[i + 3];
        float w0 = g_cw[i], w1 = g_cw[i + 1], w2 = g_cw[i + 2], w3 = g_cw[i + 3];
        float4 v0 = x4[(size_t)s0 * 32 + lane];
        float4 v1 = x4[(size_t)s1 * 32 + lane];
        float4 v2 = x4[(size_t)s2 * 32 + lane];
        float4 v3 = x4[(size_t)s3 * 32 + lane];
        acc.x += w0 * v0.x + w1 * v1.x + w2 * v2.x + w3 * v3.x;
        acc.y += w0 * v0.y + w1 * v1.y + w2 * v2.y + w3 * v3.y;
        acc.z += w0 * v0.z + w1 * v1.z + w2 * v2.z + w3 * v3.z;
        acc.w += w0 * v0.w + w1 * v1.w + w2 * v2.w + w3 * v3.w;
    }
    for (; i < e; i++) {
        int s0 = g_csrc[i];
        float w0 = g_cw[i];
        float4 v0 = x4[(size_t)s0 * 32 + lane];
        acc.x += w0 * v0.x; acc.y += w0 * v0.y;
        acc.z += w0 * v0.z; acc.w += w0 * v0.w;
    }
    float4 b = ((const float4*)bias)[lane];
    acc.x = fmaxf(acc.x + b.x, 0.f);
    acc.y = fmaxf(acc.y + b.y, 0.f);
    acc.z = fmaxf(acc.z + b.z, 0.f);
    acc.w = fmaxf(acc.w + b.w, 0.f);
    if (addsrc) {
        float4 a = ((const float4*)addsrc)[(size_t)warp * 32 + lane];
        acc.x += a.x; acc.y += a.y; acc.z += a.z; acc.w += a.w;
    }
    ((float4*)out)[(size_t)warp * 32 + lane] = acc;
}

// ---------------- pool + project + normalize ----------------
__global__ void pool_kernel(const float* __restrict__ h, const float* __restrict__ Wp,
                            const float* __restrict__ bp, const float* __restrict__ size_subg,
                            const int* __restrict__ target, float* __restrict__ out, int SZ) {
    int b = blockIdx.x, j = threadIdx.x;
    __shared__ float ps[128];
    __shared__ float red[128];
    int base = b * SZ;
    float sum = 0.f;
    for (int r = 0; r < SZ; r++) sum += h[(size_t)(base + r) * 128 + j];
    float pooled = sum / size_subg[b] + h[(size_t)target[b] * 128 + j];
    ps[j] = pooled;
    __syncthreads();
    float acc = bp[j];
    #pragma unroll 8
    for (int k = 0; k < 128; k++) acc += ps[k] * Wp[k * 128 + j];
    acc = fmaxf(acc, 0.f);
    red[j] = acc * acc;
    __syncthreads();
    for (int s = 64; s > 0; s >>= 1) {
        if (j < s) red[j] += red[j + s];
        __syncthreads();
    }
    float norm = sqrtf(red[0]);
    out[(size_t)b * 128 + j] = acc / fmaxf(norm, 1e-12f);
}

// ---------------- launch ----------------
extern "C" void kernel_launch(void* const* d_in, const int* in_sizes, int n_in,
                              void* d_out, int out_size) {
    const float* feat      = (const float*)d_in[0];
    const float* edge_w    = (const float*)d_in[1];
    const float* W1        = (const float*)d_in[2];
    const float* b1        = (const float*)d_in[3];
    const float* W2        = (const float*)d_in[4];
    const float* b2        = (const float*)d_in[5];
    const float* Wp        = (const float*)d_in[6];
    const float* bp        = (const float*)d_in[7];
    const float* size_subg = (const float*)d_in[8];
    const int*   edge_src  = (const int*)d_in[9];
    const int*   edge_dst  = (const int*)d_in[10];
    const int*   target    = (const int*)d_in[12];
    float* out = (float*)d_out;

    int N = in_sizes[0] / D;
    int E = in_sizes[1];
    int B = in_sizes[8];
    int SZ = N / B;

    void *p_tmp, *p_h1, *p_h, *p_counts;
    cudaGetSymbolAddress(&p_tmp,    g_tmp);
    cudaGetSymbolAddress(&p_h1,     g_h1);
    cudaGetSymbolAddress(&p_h,      g_h);
    cudaGetSymbolAddress(&p_counts, g_counts);
    float* tmp = (float*)p_tmp;
    float* h1  = (float*)p_h1;
    float* h   = (float*)p_h;

    const int GEMM_SMEM = 4 * 128 * STR * 2;   // 139264 B
    cudaFuncSetAttribute(gemm128_kernel, cudaFuncAttributeMaxDynamicSharedMemorySize,
                         GEMM_SMEM);

    int eb = (E + 255) / 256;
    int sb = (N + 1023) / 1024;
    int gemm_blocks = (N + 127) / 128;
    int spmm_blocks = (N * 32 + 255) / 256;

    // --- enqueue order keeps gemm1 at the profiled slot (launch idx 4) ---
    cudaMemsetAsync(p_counts, 0, (size_t)N * sizeof(int), 0);               // 0
    hist_kernel<<<eb, 256>>>(edge_dst, E);                                  // 1
    scan1_kernel<<<sb, 1024>>>(N);                                          // 2
    scan2_kernel<<<1, 256>>>(sb);                                           // 3
    gemm128_kernel<<<gemm_blocks, 512, GEMM_SMEM>>>(feat, W1, tmp, N);      // 4 (profiled)
    scan3_kernel<<<sb, 1024>>>(N, E);                                       // 5
    scatter_kernel<<<eb, 256>>>(edge_src, edge_dst, edge_w, E);             // 6

    // --- layer 1 SpMM: h1 = relu(A @ tmp + b1) ---
    spmm_kernel<<<spmm_blocks, 256>>>(tmp, b1, h1, nullptr, N);

    // --- layer 2: tmp = h1 @ W2 ; h = h1 + relu(A @ tmp + b2) ---
    gemm128_kernel<<<gemm_blocks, 512, GEMM_SMEM>>>(h1, W2, tmp, N);
    spmm_kernel<<<spmm_blocks, 256>>>(tmp, b2, h, h1, N);

    // --- pool + project + normalize ---
    pool_kernel<<<B, 128>>>(h, Wp, bp, size_subg, target, out, SZ);
}

// round 17
// speedup vs baseline: 1.0458x; 1.0458x over previous
#include <cuda_runtime.h>
#include <cuda_bf16.h>
#include <cstdint>

#define D 128
#define MAXN 100000
#define MAXE 1600000
#define STR 136   // bf16 row stride in smem (272B -> conflict-free ldmatrix)

// ---- static scratch (no allocations allowed) ----
__device__ float g_tmp[(size_t)MAXN * D];
__device__ float g_h1 [(size_t)MAXN * D];
__device__ float g_h  [(size_t)MAXN * D];
__device__ int   g_counts[MAXN];
__device__ int   g_rptr [MAXN + 1];
__device__ int   g_cursor[MAXN];
__device__ int   g_boff [256];
__device__ int   g_csrc [MAXE];
__device__ float g_cw   [MAXE];

// ---------------- CSR build ----------------
__global__ void hist_kernel(const int* __restrict__ dst, int E) {
    int e = blockIdx.x * blockDim.x + threadIdx.x;
    if (e < E) atomicAdd(&g_counts[dst[e]], 1);
}

__global__ void scan1_kernel(int n) {
    __shared__ int wsum[32];
    int tid = threadIdx.x, lane = tid & 31, wid = tid >> 5;
    int i = blockIdx.x * 1024 + tid;
    int v = (i < n) ? g_counts[i] : 0;
    int incl = v;
    #pragma unroll
    for (int d = 1; d < 32; d <<= 1) {
        int t = __shfl_up_sync(0xffffffffu, incl, d);
        if (lane >= d) incl += t;
    }
    if (lane == 31) wsum[wid] = incl;
    __syncthreads();
    if (wid == 0) {
        int s = wsum[lane];
        #pragma unroll
        for (int d = 1; d < 32; d <<= 1) {
            int t = __shfl_up_sync(0xffffffffu, s, d);
            if (lane >= d) s += t;
        }
        wsum[lane] = s;
    }
    __syncthreads();
    int add = wid ? wsum[wid - 1] : 0;
    int excl = add + incl - v;
    if (i < n) g_rptr[i] = excl;
    if (tid == 1023) g_boff[blockIdx.x] = excl + v;
}

__global__ void scan2_kernel(int nb) {
    __shared__ int wsum[8];
    int tid = threadIdx.x, lane = tid & 31, wid = tid >> 5;
    int v = (tid < nb) ? g_boff[tid] : 0;
    int incl = v;
    #pragma unroll
    for (int d = 1; d < 32; d <<= 1) {
        int t = __shfl_up_sync(0xffffffffu, incl, d);
        if (lane >= d) incl += t;
    }
    if (lane == 31) wsum[wid] = incl;
    __syncthreads();
    if (wid == 0 && lane < 8) {
        int s = wsum[lane];
        #pragma unroll
        for (int d = 1; d < 8; d <<= 1) {
            int t = __shfl_up_sync(0xffu, s, d);
            if (lane >= d) s += t;
        }
        wsum[lane] = s;
    }
    __syncthreads();
    int add = wid ? wsum[wid - 1] : 0;
    if (tid < nb) g_boff[tid] = add + incl - v;
}

__global__ void scan3_kernel(int n, int E) {
    int i = blockIdx.x * 1024 + threadIdx.x;
    if (i < n) {
        int v = g_rptr[i] + g_boff[blockIdx.x];
        g_rptr[i] = v;
        g_cursor[i] = v;
    }
    if (i == 0) g_rptr[n] = E;
}

__global__ void scatter_kernel(const int* __restrict__ src, const int* __restrict__ dst,
                               const float* __restrict__ w, int E) {
    int e = blockIdx.x * blockDim.x + threadIdx.x;
    if (e < E) {
        int d = dst[e];
        int p = atomicAdd(&g_cursor[d], 1);
        g_csrc[p] = src[e];
        g_cw[p]   = w[e];
    }
}

// ================= HMMA (mma.sync) helpers =================
__device__ __forceinline__ uint32_t smem_u32(const void* p) {
    uint32_t a;
    asm("{ .reg .u64 t; cvta.to.shared.u64 t, %1; cvt.u32.u64 %0, t; }" : "=r"(a) : "l"(p));
    return a;
}
__device__ __forceinline__ void ldsm_x4(uint32_t* r, uint32_t addr) {
    asm volatile("ldmatrix.sync.aligned.m8n8.x4.shared.b16 {%0,%1,%2,%3}, [%4];"
                 : "=r"(r[0]), "=r"(r[1]), "=r"(r[2]), "=r"(r[3]) : "r"(addr));
}
__device__ __forceinline__ void ldsm_x4_t(uint32_t* r, uint32_t addr) {
    asm volatile("ldmatrix.sync.aligned.m8n8.x4.trans.shared.b16 {%0,%1,%2,%3}, [%4];"
                 : "=r"(r[0]), "=r"(r[1]), "=r"(r[2]), "=r"(r[3]) : "r"(addr));
}
__device__ __forceinline__ void mma_bf16(float* c, const uint32_t* a, uint32_t b0, uint32_t b1) {
    asm volatile("mma.sync.aligned.m16n8k16.row.col.f32.bf16.bf16.f32 "
                 "{%0,%1,%2,%3}, {%4,%5,%6,%7}, {%8,%9}, {%0,%1,%2,%3};"
                 : "+f"(c[0]), "+f"(c[1]), "+f"(c[2]), "+f"(c[3])
                 : "r"(a[0]), "r"(a[1]), "r"(a[2]), "r"(a[3]), "r"(b0), "r"(b1));
}
__device__ __forceinline__ uint32_t pack_hi(float x, float y, uint32_t& lo_out) {
    __nv_bfloat16 hx = __float2bfloat16_rn(x);
    __nv_bfloat16 hy = __float2bfloat16_rn(y);
    __nv_bfloat16 lx = __float2bfloat16_rn(x - __bfloat162float(hx));
    __nv_bfloat16 ly = __float2bfloat16_rn(y - __bfloat162float(hy));
    lo_out = (uint32_t)__bfloat16_as_ushort(lx) | ((uint32_t)__bfloat16_as_ushort(ly) << 16);
    return (uint32_t)__bfloat16_as_ushort(hx) | ((uint32_t)__bfloat16_as_ushort(hy) << 16);
}

// ---------------- GEMM via mma.sync: Y[n,128] = X[n,128] @ W[128,128] ----------------
// bf16 two-term split (Xh·Wh + Xl·Wh + Xh·Wl), fp32 accum.
// 256 threads = 8 warps in 2x4 grid; warp tile 64 rows x 32 cols
// (12 ldsm.x4 per 48 mma -> 33% less LDSM traffic than 32x32 tiling).
__global__ void __launch_bounds__(256)
gemm128_kernel(const float* __restrict__ X, const float* __restrict__ W,
               float* __restrict__ Y, int nrows) {
    extern __shared__ char smc[];
    uint32_t sbase = smem_u32(smc);
    const uint32_t SZA = 128 * STR * 2;       // 34816 B per array
    uint32_t sAhi = sbase, sAlo = sbase + SZA, sWhi = sbase + 2 * SZA, sWlo = sbase + 3 * SZA;
    int tid = threadIdx.x, lane = tid & 31, w = tid >> 5;
    int wm = w >> 2, wn = w & 3;              // wm in {0,1}: 64-row strip; wn in {0..3}: 32-col strip
    int row0 = blockIdx.x * 128;

    // --- prep W: hi/lo bf16 (each thread: 32 float2) ---
    {
        int r = tid >> 1, q = (tid & 1) * 64;
        const float2* src = (const float2*)&W[r * 128 + q];
        uint32_t* dh = (uint32_t*)(smc + 2 * SZA) + (r * STR + q) / 2;
        uint32_t* dl = (uint32_t*)(smc + 3 * SZA) + (r * STR + q) / 2;
        #pragma unroll 8
        for (int i = 0; i < 32; i++) {
            float2 v = src[i];
            uint32_t lo;
            uint32_t hi = pack_hi(v.x, v.y, lo);
            dh[i] = hi; dl[i] = lo;
        }
    }
    // --- prep X tile ---
    {
        int r = tid >> 1, q = (tid & 1) * 64;
        int gr = row0 + r;
        uint32_t* dh = (uint32_t*)smc + (r * STR + q) / 2;
        uint32_t* dl = (uint32_t*)(smc + SZA) + (r * STR + q) / 2;
        if (gr < nrows) {
            const float2* src = (const float2*)&X[(size_t)gr * 128 + q];
            #pragma unroll 8
            for (int i = 0; i < 32; i++) {
                float2 v = src[i];
                uint32_t lo;
                uint32_t hi = pack_hi(v.x, v.y, lo);
                dh[i] = hi; dl[i] = lo;
            }
        } else {
            #pragma unroll 8
            for (int i = 0; i < 32; i++) { dh[i] = 0u; dl[i] = 0u; }
        }
    }
    __syncthreads();

    // acc[mt][nt][g][4]: mt in 0..3 (16-row tiles), nt in 0..1 (16-col tiles), g = n8 group
    float acc[4][2][2][4];
    #pragma unroll
    for (int mt = 0; mt < 4; mt++)
        #pragma unroll
        for (int nt = 0; nt < 2; nt++)
            #pragma unroll
            for (int g = 0; g < 2; g++)
                #pragma unroll
                for (int c = 0; c < 4; c++) acc[mt][nt][g][c] = 0.f;

    uint32_t aoff[4], boff[2];
    #pragma unroll
    for (int mt = 0; mt < 4; mt++)
        aoff[mt] = (uint32_t)(((wm * 64 + mt * 16 + (lane & 15)) * STR + (lane >> 4) * 8) * 2);
    #pragma unroll
    for (int nt = 0; nt < 2; nt++)
        boff[nt] = (uint32_t)(((lane & 15) * STR + wn * 32 + nt * 16 + (lane >> 4) * 8) * 2);

    // double-buffered fragments
    uint32_t Ah[2][4][4], Al[2][4][4], Bh[2][2][4], Bl[2][2][4];

    #define LOAD_FRAGS(buf, kc) do {                                          \
        _Pragma("unroll")                                                     \
        for (int mt = 0; mt < 4; mt++) {                                      \
            ldsm_x4(Ah[buf][mt], sAhi + aoff[mt] + (uint32_t)((kc) * 32));    \
            ldsm_x4(Al[buf][mt], sAlo + aoff[mt] + (uint32_t)((kc) * 32));    \
        }                                                                     \
        _Pragma("unroll")                                                     \
        for (int nt = 0; nt < 2; nt++) {                                      \
            ldsm_x4_t(Bh[buf][nt], sWhi + boff[nt] + (uint32_t)((kc) * 16 * STR * 2)); \
            ldsm_x4_t(Bl[buf][nt], sWlo + boff[nt] + (uint32_t)((kc) * 16 * STR * 2)); \
        }                                                                     \
    } while (0)

    #define COMPUTE(buf) do {                                                 \
        _Pragma("unroll")                                                     \
        for (int mt = 0; mt < 4; mt++)                                        \
            _Pragma("unroll")                                                 \
            for (int nt = 0; nt < 2; nt++) {                                  \
                float* c0 = acc[mt][nt][0];                                   \
                float* c1 = acc[mt][nt][1];                                   \
                mma_bf16(c0, Ah[buf][mt], Bh[buf][nt][0], Bh[buf][nt][1]);    \
                mma_bf16(c0, Al[buf][mt], Bh[buf][nt][0], Bh[buf][nt][1]);    \
                mma_bf16(c0, Ah[buf][mt], Bl[buf][nt][0], Bl[buf][nt][1]);    \
                mma_bf16(c1, Ah[buf][mt], Bh[buf][nt][2], Bh[buf][nt][3]);    \
                mma_bf16(c1, Al[buf][mt], Bh[buf][nt][2], Bh[buf][nt][3]);    \
                mma_bf16(c1, Ah[buf][mt], Bl[buf][nt][2], Bl[buf][nt][3]);    \
            }                                                                 \
    } while (0)

    LOAD_FRAGS(0, 0);
    #pragma unroll
    for (int kc = 0; kc < 8; kc++) {
        if (kc < 7) LOAD_FRAGS((kc + 1) & 1, kc + 1);
        COMPUTE(kc & 1);
    }
    #undef LOAD_FRAGS
    #undef COMPUTE

    // --- epilogue ---
    #pragma unroll
    for (int mt = 0; mt < 4; mt++) {
        int rbase = row0 + wm * 64 + mt * 16 + (lane >> 2);
        bool ok0 = rbase < nrows, ok1 = (rbase + 8) < nrows;
        #pragma unroll
        for (int nt = 0; nt < 2; nt++)
            #pragma unroll
            for (int g = 0; g < 2; g++) {
                int col = wn * 32 + nt * 16 + g * 8 + 2 * (lane & 3);
                float* c = acc[mt][nt][g];
                if (ok0) *(float2*)&Y[(size_t)rbase * 128 + col]       = make_float2(c[0], c[1]);
                if (ok1) *(float2*)&Y[(size_t)(rbase + 8) * 128 + col] = make_float2(c[2], c[3]);
            }
    }
}

// ---------------- SpMM (CSR gather) + bias + relu (+ residual add) ----------------
__global__ void spmm_kernel(const float* __restrict__ x, const float* __restrict__ bias,
                            float* __restrict__ out, const float* __restrict__ addsrc, int n) {
    int warp = (blockIdx.x * blockDim.x + threadIdx.x) >> 5;
    int lane = threadIdx.x & 31;
    if (warp >= n) return;
    int s = g_rptr[warp], e = g_rptr[warp + 1];
    const float4* x4 = (const float4*)x;
    float4 acc = make_float4(0.f, 0.f, 0.f, 0.f);
    int i = s;
    for (; i + 3 < e; i += 4) {
        int s0 = g_csrc[i], s1 = g_csrc[i + 1], s2 = g_csrc[i + 2], s3 = g_csrc[i + 3];
        float w0 = g_cw[i], w1 = g_cw[i + 1], w2 = g_cw[i + 2], w3 = g_cw[i + 3];
        float4 v0 = x4[(size_t)s0 * 32 + lane];
        float4 v1 = x4[(size_t)s1 * 32 + lane];
        float4 v2 = x4[(size_t)s2 * 32 + lane];
        float4 v3 = x4[(size_t)s3 * 32 + lane];
        acc.x += w0 * v0.x + w1 * v1.x + w2 * v2.x + w3 * v3.x;
        acc.y += w0 * v0.y + w1 * v1.y + w2 * v2.y + w3 * v3.y;
        acc.z += w0 * v0.z + w1 * v1.z + w2 * v2.z + w3 * v3.z;
        acc.w += w0 * v0.w + w1 * v1.w + w2 * v2.w + w3 * v3.w;
    }
    for (; i < e; i++) {
        int s0 = g_csrc[i];
        float w0 = g_cw[i];
        float4 v0 = x4[(size_t)s0 * 32 + lane];
        acc.x += w0 * v0.x; acc.y += w0 * v0.y;
        acc.z += w0 * v0.z; acc.w += w0 * v0.w;
    }
    float4 b = ((const float4*)bias)[lane];
    acc.x = fmaxf(acc.x + b.x, 0.f);
    acc.y = fmaxf(acc.y + b.y, 0.f);
    acc.z = fmaxf(acc.z + b.z, 0.f);
    acc.w = fmaxf(acc.w + b.w, 0.f);
    if (addsrc) {
        float4 a = ((const float4*)addsrc)[(size_t)warp * 32 + lane];
        acc.x += a.x; acc.y += a.y; acc.z += a.z; acc.w += a.w;
    }
    ((float4*)out)[(size_t)warp * 32 + lane] = acc;
}

// ---------------- pool + project + normalize ----------------
__global__ void pool_kernel(const float* __restrict__ h, const float* __restrict__ Wp,
                            const float* __restrict__ bp, const float* __restrict__ size_subg,
                            const int* __restrict__ target, float* __restrict__ out, int SZ) {
    int b = blockIdx.x, j = threadIdx.x;
    __shared__ float ps[128];
    __shared__ float red[128];
    int base = b * SZ;
    float sum = 0.f;
    for (int r = 0; r < SZ; r++) sum += h[(size_t)(base + r) * 128 + j];
    float pooled = sum / size_subg[b] + h[(size_t)target[b] * 128 + j];
    ps[j] = pooled;
    __syncthreads();
    float acc = bp[j];
    #pragma unroll 8
    for (int k = 0; k < 128; k++) acc += ps[k] * Wp[k * 128 + j];
    acc = fmaxf(acc, 0.f);
    red[j] = acc * acc;
    __syncthreads();
    for (int s = 64; s > 0; s >>= 1) {
        if (j < s) red[j] += red[j + s];
        __syncthreads();
    }
    float norm = sqrtf(red[0]);
    out[(size_t)b * 128 + j] = acc / fmaxf(norm, 1e-12f);
}

// ---------------- launch ----------------
extern "C" void kernel_launch(void* const* d_in, const int* in_sizes, int n_in,
                              void* d_out, int out_size) {
    const float* feat      = (const float*)d_in[0];
    const float* edge_w    = (const float*)d_in[1];
    const float* W1        = (const float*)d_in[2];
    const float* b1        = (const float*)d_in[3];
    const float* W2        = (const float*)d_in[4];
    const float* b2        = (const float*)d_in[5];
    const float* Wp        = (const float*)d_in[6];
    const float* bp        = (const float*)d_in[7];
    const float* size_subg = (const float*)d_in[8];
    const int*   edge_src  = (const int*)d_in[9];
    const int*   edge_dst  = (const int*)d_in[10];
    const int*   target    = (const int*)d_in[12];
    float* out = (float*)d_out;

    int N = in_sizes[0] / D;
    int E = in_sizes[1];
    int B = in_sizes[8];
    int SZ = N / B;

    void *p_tmp, *p_h1, *p_h, *p_counts;
    cudaGetSymbolAddress(&p_tmp,    g_tmp);
    cudaGetSymbolAddress(&p_h1,     g_h1);
    cudaGetSymbolAddress(&p_h,      g_h);
    cudaGetSymbolAddress(&p_counts, g_counts);
    float* tmp = (float*)p_tmp;
    float* h1  = (float*)p_h1;
    float* h   = (float*)p_h;

    const int GEMM_SMEM = 4 * 128 * STR * 2;   // 139264 B
    cudaFuncSetAttribute(gemm128_kernel, cudaFuncAttributeMaxDynamicSharedMemorySize,
                         GEMM_SMEM);

    // lazy host-side resources for the graph fork (created once; identical
    // launch pattern every call -> capture/replay deterministic)
    static cudaStream_t s2 = nullptr;
    static cudaEvent_t ev_fork = nullptr, ev_join = nullptr;
    if (!s2) {
        cudaStreamCreateWithFlags(&s2, cudaStreamNonBlocking);
        cudaEventCreateWithFlags(&ev_fork, cudaEventDisableTiming);
        cudaEventCreateWithFlags(&ev_join, cudaEventDisableTiming);
    }

    int eb = (E + 255) / 256;
    int sb = (N + 1023) / 1024;
    int gemm_blocks = (N + 127) / 128;
    int spmm_blocks = (N * 32 + 255) / 256;

    // --- fork: CSR build on s2 concurrent with gemm1 on main stream ---
    cudaEventRecord(ev_fork, 0);
    cudaStreamWaitEvent(s2, ev_fork, 0);

    cudaMemsetAsync(p_counts, 0, (size_t)N * sizeof(int), s2);
    hist_kernel<<<eb, 256, 0, s2>>>(edge_dst, E);
    scan1_kernel<<<sb, 1024, 0, s2>>>(N);
    scan2_kernel<<<1, 256, 0, s2>>>(sb);
    scan3_kernel<<<sb, 1024, 0, s2>>>(N, E);
    scatter_kernel<<<eb, 256, 0, s2>>>(edge_src, edge_dst, edge_w, E);

    gemm128_kernel<<<gemm_blocks, 256, GEMM_SMEM>>>(feat, W1, tmp, N);

    cudaEventRecord(ev_join, s2);
    cudaStreamWaitEvent(0, ev_join, 0);

    // --- layer 1 SpMM: h1 = relu(A @ tmp + b1) ---
    spmm_kernel<<<spmm_blocks, 256>>>(tmp, b1, h1, nullptr, N);

    // --- layer 2: tmp = h1 @ W2 ; h = h1 + relu(A @ tmp + b2) ---
    gemm128_kernel<<<gemm_blocks, 256, GEMM_SMEM>>>(h1, W2, tmp, N);
    spmm_kernel<<<spmm_blocks, 256>>>(tmp, b2, h, h1, N);

    // --- pool + project + normalize ---
    pool_kernel<<<B, 128>>>(h, Wp, bp, size_subg, target, out, SZ);
}